// round 14
// baseline (speedup 1.0000x reference)
#include <cuda_runtime.h>

#define T_LEN 4096
#define B_SZ  512
#define NIN   42
#define NH    9
#define STRIDE (B_SZ * NH)   // 4608 floats per timestep (output)
#define EPB   4              // batch elements per block
#define NBLK  (B_SZ / EPB)   // 128 blocks
#define CH    16             // timesteps per chunk
#define NCH   (T_LEN / CH)   // 256
#define XSP   65             // padded row stride in xs

typedef unsigned long long ull;

// ---------------------------------------------------------------------------
// helpers
// ---------------------------------------------------------------------------
__device__ __forceinline__ ull ffma2(ull a, ull b, ull c) {
    ull d;
    asm("fma.rn.f32x2 %0, %1, %2, %3;" : "=l"(d) : "l"(a), "l"(b), "l"(c));
    return d;
}
__device__ __forceinline__ ull pack2(float a, float b) {
    ull r;
    asm("mov.b64 %0, {%1,%2};" : "=l"(r) : "f"(a), "f"(b));
    return r;
}
__device__ __forceinline__ void lds_v2u64(ull& a, ull& b, const void* p) {
    unsigned addr = (unsigned)__cvta_generic_to_shared(p);
    asm volatile("ld.shared.v2.u64 {%0,%1}, [%2];" : "=l"(a), "=l"(b) : "r"(addr));
}
__device__ __forceinline__ ull lds_u64(const void* p) {
    unsigned addr = (unsigned)__cvta_generic_to_shared(p);
    ull v;
    asm volatile("ld.shared.u64 %0, [%1];" : "=l"(v) : "r"(addr));
    return v;
}
__device__ __forceinline__ float2 unpack2(ull v) {
    float2 f;
    f.x = __uint_as_float((unsigned)(v & 0xffffffffull));
    f.y = __uint_as_float((unsigned)(v >> 32));
    return f;
}
__device__ __forceinline__ float tanh_ap(float x) {
    float y;
    asm("tanh.approx.f32 %0, %1;" : "=f"(y) : "f"(x));
    return y;
}
__device__ __forceinline__ int ld_acq_sh(const int* p) {
    unsigned a = (unsigned)__cvta_generic_to_shared(p);
    int v;
    asm volatile("ld.acquire.cta.shared.b32 %0, [%1];" : "=r"(v) : "r"(a));
    return v;
}
__device__ __forceinline__ int ld_vol_sh(const int* p) {
    unsigned a = (unsigned)__cvta_generic_to_shared(p);
    int v;
    asm volatile("ld.volatile.shared.b32 %0, [%1];" : "=r"(v) : "r"(a));
    return v;
}
__device__ __forceinline__ void st_rel_sh(int* p, int v) {
    unsigned a = (unsigned)__cvta_generic_to_shared(p);
    asm volatile("st.release.cta.shared.b32 [%0], %1;" :: "r"(a), "r"(v) : "memory");
}
__device__ __forceinline__ void red_rel_sh(int* p, int v) {
    unsigned a = (unsigned)__cvta_generic_to_shared(p);
    asm volatile("red.release.cta.shared.add.u32 [%0], %1;" :: "r"(a), "r"(v) : "memory");
}

// 18-lane step: lane l<9 owns (i/2,f/2) of unit l; lane 9+j owns (g,o/2) of
// unit j. ACC = gate pair from gbuf (bias folded). Wp[k] = this lane's paired
// recurrent weights. Lanes 0-8 carry h, c.
#define LSTM_STEP18(ACC, TT) do {                                             \
    ull a = (ACC);                                                            \
    _Pragma("unroll")                                                         \
    for (int k = 0; k < 9; k++) {                                             \
        float hk = __shfl_sync(0xFFFFFFFFu, h, k);                            \
        a = ffma2(Wp[k], pack2(hk, hk), a);                                   \
    }                                                                         \
    float2 v = unpack2(a);                                                    \
    float t0 = tanh_ap(v.x);                                                  \
    float t1 = tanh_ap(v.y);                                                  \
    float s0 = fmaf(0.5f, t0, 0.5f);                                          \
    float s1 = fmaf(0.5f, t1, 0.5f);                                          \
    float gg = __shfl_sync(0xFFFFFFFFu, t0, lane + 9);                        \
    float og = __shfl_sync(0xFFFFFFFFu, s1, lane + 9);                        \
    c = fmaf(s1, c, s0 * gg);                                                 \
    h = og * tanh_ap(c);                                                      \
    if (valid) out[(TT) * STRIDE + base_idx] = h;                             \
} while (0)

// ---------------------------------------------------------------------------
// Fused kernel: warps 0-3 produce gates (R12 producer, unchanged);
// warps 4-7 run the 18-lane recurrence (1 batch elem per warp).
// ---------------------------------------------------------------------------
__global__ __launch_bounds__(256, 1) void lstm_fused_kernel(
    const float* __restrict__ x,    const float* __restrict__ h_in,
    const float* __restrict__ c_in, const float* __restrict__ Wih,
    const float* __restrict__ Whh,  const float* __restrict__ bih,
    const float* __restrict__ bhh,  float* __restrict__ out)
{
    __shared__ float4 gbuf[2][CH][EPB * NH];   // gate ring: 18432 B
    __shared__ float  xs[2][NIN][XSP];         // x staging: 21840 B (k-major)
    __shared__ float2 wsH[2][NIN][10];         // paired W_ih: 6720 B
    __shared__ int ready, done;

    const int tid  = threadIdx.x;
    const int w    = tid >> 5;
    const int lane = tid & 31;
    const int b0   = blockIdx.x * EPB;

    // stage paired, pre-scaled W_ih: wsH[h][k][j] = (W[2h][j][k], W[2h+1][j][k])
    for (int i = tid; i < NIN * 18; i += 256) {
        int k = i / 18, rem = i - 18 * k;
        int hh = rem / 9, j = rem - 9 * hh;
        float w0 = Wih[((2 * hh) * NH + j) * NIN + k];
        float w1 = Wih[((2 * hh + 1) * NH + j) * NIN + k];
        if (hh == 0) { w0 *= 0.5f; w1 *= 0.5f; }   // i, f
        else         { w1 *= 0.5f; }               // o
        wsH[hh][k][j] = make_float2(w0, w1);
    }
    if (tid == 0) { ready = 0; done = 0; }
    __syncthreads();

    if (w >= EPB) {
        // ====================== COMPUTE WARP (wid 4-7, 1 elem, 18 lanes) =====
        const int cw = w - EPB;           // batch slot 0..3
        const int b  = b0 + cw;
        const bool isIF = (lane < 9);
        const int j  = isIF ? lane : ((lane < 18) ? lane - 9 : 8);
        const bool valid = isIF;

        // per-lane paired recurrent weights
        ull Wp[NH];
        #pragma unroll
        for (int k = 0; k < NH; k++) {
            if (isIF) {
                Wp[k] = pack2(0.5f * Whh[(0 * NH + j) * NH + k],
                              0.5f * Whh[(1 * NH + j) * NH + k]);
            } else {
                Wp[k] = pack2(       Whh[(2 * NH + j) * NH + k],
                              0.5f * Whh[(3 * NH + j) * NH + k]);
            }
        }
        float h = h_in[b * NH + j];
        float c = c_in[b * NH + j];
        const int base_idx = b * NH + j;
        const int u = cw * NH + j;
        // lane's half of the float4 gate slot: bytes [0,8) for (i,f),
        // [8,16) for (g,o)
        const int hoff = isIF ? 0 : 1;

        for (int cch = 0; cch < NCH; cch++) {
            const int buf = cch & 1;
            const int t0s = cch * CH;
            if (ld_acq_sh(&ready) < cch + 1) {
                while (ld_acq_sh(&ready) < cch + 1) __nanosleep(32);
            }
            const ull* xb = (const ull*)&gbuf[buf][0][u] + hoff;
            // software-pipelined gate-pair loads
            ull p = lds_u64(xb);
            #pragma unroll
            for (int s = 0; s < CH; s++) {
                ull n = p;
                if (s + 1 < CH) n = lds_u64(xb + (s + 1) * (EPB * NH) * 2);
                LSTM_STEP18(p, t0s + s);
                p = n;
            }
            __syncwarp();
            if (lane == 0) red_rel_sh(&done, 1);
        }

        if (valid) {
            out[(size_t)T_LEN * STRIDE + base_idx]          = h;  // hn
            out[(size_t)T_LEN * STRIDE + STRIDE + base_idx] = c;  // cn
        }
    } else {
        // ====================== PRODUCER WARP (wid 0-3, unchanged) ===========
        const int half = w & 1;
        const int row  = (w >> 1) * 32 + lane;   // 0..63
        const int tl   = row >> 2;               // local t
        const int bb   = row & 3;                // batch slot

        ull bias[9];
        #pragma unroll
        for (int j = 0; j < 9; j++) {
            float bb0 = bih[(2 * half) * NH + j]     + bhh[(2 * half) * NH + j];
            float bb1 = bih[(2 * half + 1) * NH + j] + bhh[(2 * half + 1) * NH + j];
            if (half == 0) { bb0 *= 0.5f; bb1 *= 0.5f; }
            else           { bb1 *= 0.5f; }
            bias[j] = pack2(bb0, bb1);
        }

        const int sr = tid >> 1;
        const int sp = tid & 1;
        const int k2base = sp * 10;
        const float2* xsrc0 = (const float2*)
            (x + ((size_t)(sr >> 2) * B_SZ + (b0 + (sr & 3))) * NIN) + k2base;
        const size_t chstep = (size_t)CH * B_SZ * NIN / 2;

        // prologue: stage chunk 0
        {
            float2 xr[11];
            #pragma unroll
            for (int q = 0; q < 11; q++) xr[q] = xsrc0[q];
            #pragma unroll
            for (int q = 0; q < 11; q++) {
                xs[0][2 * (k2base + q)][sr]     = xr[q].x;
                xs[0][2 * (k2base + q) + 1][sr] = xr[q].y;
            }
            asm volatile("bar.sync 1, 128;" ::: "memory");
        }

        for (int cch = 0; cch < NCH; cch++) {
            const int buf  = cch & 1;
            const int nbuf = buf ^ 1;

            float2 xr[11];
            if (cch + 1 < NCH) {
                const float2* src = xsrc0 + (size_t)(cch + 1) * chstep;
                #pragma unroll
                for (int q = 0; q < 11; q++) xr[q] = src[q];
            }

            if (cch >= 2) {
                const int need = EPB * (cch - 1);
                if (ld_vol_sh(&done) < need) {
                    while (ld_vol_sh(&done) < need) __nanosleep(64);
                }
            }

            ull acc[9];
            #pragma unroll
            for (int j = 0; j < 9; j++) acc[j] = bias[j];

            const float*  xb = &xs[buf][0][row];
            const float2* wb = &wsH[half][0][0];
            #pragma unroll
            for (int k = 0; k < NIN; k++) {
                float xv = xb[(size_t)k * XSP];
                ull xx = pack2(xv, xv);
                const float2* wk = wb + (size_t)k * 10;
                ull wj[9];
                lds_v2u64(wj[0], wj[1], wk);
                lds_v2u64(wj[2], wj[3], wk + 2);
                lds_v2u64(wj[4], wj[5], wk + 4);
                lds_v2u64(wj[6], wj[7], wk + 6);
                wj[8] = lds_u64(wk + 8);
                #pragma unroll
                for (int j = 0; j < 9; j++) acc[j] = ffma2(wj[j], xx, acc[j]);
            }

            {
                ull* base = (ull*)&gbuf[buf][tl][bb * NH] + half;
                #pragma unroll
                for (int j = 0; j < 9; j++) base[2 * j] = acc[j];
            }
            asm volatile("bar.sync 1, 128;" ::: "memory");
            if (tid == 0) st_rel_sh(&ready, cch + 1);

            if (cch + 1 < NCH) {
                #pragma unroll
                for (int q = 0; q < 11; q++) {
                    xs[nbuf][2 * (k2base + q)][sr]     = xr[q].x;
                    xs[nbuf][2 * (k2base + q) + 1][sr] = xr[q].y;
                }
                asm volatile("bar.sync 1, 128;" ::: "memory");
            }
        }
    }
}

// ---------------------------------------------------------------------------
extern "C" void kernel_launch(void* const* d_in, const int* in_sizes, int n_in,
                              void* d_out, int out_size) {
    const float* x   = (const float*)d_in[0];
    const float* h   = (const float*)d_in[1];
    const float* c   = (const float*)d_in[2];
    const float* Wih = (const float*)d_in[3];
    const float* Whh = (const float*)d_in[4];
    const float* bih = (const float*)d_in[5];
    const float* bhh = (const float*)d_in[6];
    float* out = (float*)d_out;

    lstm_fused_kernel<<<NBLK, 256>>>(x, h, c, Wih, Whh, bih, bhh, out);
}

// round 15
// speedup vs baseline: 1.1790x; 1.1790x over previous
#include <cuda_runtime.h>
#include <cstdint>

#define T_LEN 4096
#define B_SZ  512
#define NIN   42
#define NH    9
#define STRIDE (B_SZ * NH)   // 4608 floats per timestep (output)
#define EPB   4              // batch elements per block
#define NBLK  (B_SZ / EPB)   // 128 blocks
#define CH    16             // timesteps per chunk
#define NCH   (T_LEN / CH)   // 256

// bf16 tile region (112-byte row pitch, conflict-free for frag loads)
#define AH_O  0              // A hi: 64 x 56 bf16 (7168 B)
#define AL_O  7168           // A lo
#define BH_O  14336          // B hi: 40 x 56 bf16 (4480 B)
#define BL_O  18816          // B lo
#define TILES_BYTES 23296

typedef unsigned long long ull;

// ---------------------------------------------------------------------------
// helpers
// ---------------------------------------------------------------------------
__device__ __forceinline__ ull ffma2(ull a, ull b, ull c) {
    ull d;
    asm("fma.rn.f32x2 %0, %1, %2, %3;" : "=l"(d) : "l"(a), "l"(b), "l"(c));
    return d;
}
__device__ __forceinline__ ull pack2(float a, float b) {
    ull r;
    asm("mov.b64 %0, {%1,%2};" : "=l"(r) : "f"(a), "f"(b));
    return r;
}
__device__ __forceinline__ void lds_v2u64(ull& a, ull& b, const void* p) {
    unsigned addr = (unsigned)__cvta_generic_to_shared(p);
    asm volatile("ld.shared.v2.u64 {%0,%1}, [%2];" : "=l"(a), "=l"(b) : "r"(addr));
}
__device__ __forceinline__ unsigned lds_b32(unsigned addr) {
    unsigned v;
    asm volatile("ld.shared.b32 %0, [%1];" : "=r"(v) : "r"(addr));
    return v;
}
__device__ __forceinline__ float2 unpack2(ull v) {
    float2 f;
    f.x = __uint_as_float((unsigned)(v & 0xffffffffull));
    f.y = __uint_as_float((unsigned)(v >> 32));
    return f;
}
__device__ __forceinline__ float tanh_ap(float x) {
    float y;
    asm("tanh.approx.f32 %0, %1;" : "=f"(y) : "f"(x));
    return y;
}
__device__ __forceinline__ int ld_acq_sh(const int* p) {
    unsigned a = (unsigned)__cvta_generic_to_shared(p);
    int v;
    asm volatile("ld.acquire.cta.shared.b32 %0, [%1];" : "=r"(v) : "r"(a));
    return v;
}
__device__ __forceinline__ int ld_vol_sh(const int* p) {
    unsigned a = (unsigned)__cvta_generic_to_shared(p);
    int v;
    asm volatile("ld.volatile.shared.b32 %0, [%1];" : "=r"(v) : "r"(a));
    return v;
}
__device__ __forceinline__ void st_rel_sh(int* p, int v) {
    unsigned a = (unsigned)__cvta_generic_to_shared(p);
    asm volatile("st.release.cta.shared.b32 [%0], %1;" :: "r"(a), "r"(v) : "memory");
}
__device__ __forceinline__ void red_rel_sh(int* p, int v) {
    unsigned a = (unsigned)__cvta_generic_to_shared(p);
    asm volatile("red.release.cta.shared.add.u32 [%0], %1;" :: "r"(a), "r"(v) : "memory");
}
__device__ __forceinline__ void sts_zero4(unsigned addr) {
    asm volatile("st.shared.v4.b32 [%0], {%1,%1,%1,%1};" :: "r"(addr), "r"(0) : "memory");
}
__device__ __forceinline__ unsigned smem_u32(const void* p) {
    return (unsigned)__cvta_generic_to_shared(p);
}
// bf16 round-to-nearest-even from fp32 bits
__device__ __forceinline__ unsigned f2bf(float v) {
    unsigned u = __float_as_uint(v);
    return (u + 0x7FFFu + ((u >> 16) & 1u)) >> 16;
}
__device__ __forceinline__ float bf2f(unsigned b) {
    return __uint_as_float(b << 16);
}
__device__ __forceinline__ void mma_bf16(float& d0, float& d1, float& d2, float& d3,
                                         unsigned a0, unsigned a1, unsigned a2, unsigned a3,
                                         unsigned b0, unsigned b1) {
    asm volatile(
        "mma.sync.aligned.m16n8k16.row.col.f32.bf16.bf16.f32 "
        "{%0,%1,%2,%3}, {%4,%5,%6,%7}, {%8,%9}, {%0,%1,%2,%3};"
        : "+f"(d0), "+f"(d1), "+f"(d2), "+f"(d3)
        : "r"(a0), "r"(a1), "r"(a2), "r"(a3), "r"(b0), "r"(b1));
}

// Packed compute step (R12): P01=(i/2,f/2), P23=(g,o/2); biases folded in.
#define LSTM_STEP_P(P01, P23, TT) do {                                        \
    ull a01 = (P01), a23 = (P23);                                             \
    _Pragma("unroll")                                                         \
    for (int k = 0; k < 9; k++) {                                             \
        float hk = __shfl_sync(0xFFFFFFFFu, h, k);                            \
        ull hh = pack2(hk, hk);                                               \
        a01 = ffma2(W01[k], hh, a01);                                         \
        a23 = ffma2(W23[k], hh, a23);                                         \
    }                                                                         \
    float2 v0 = unpack2(a01);                                                 \
    float2 v1 = unpack2(a23);                                                 \
    float ig = fmaf(0.5f, tanh_ap(v0.x), 0.5f);                               \
    float fg = fmaf(0.5f, tanh_ap(v0.y), 0.5f);                               \
    float gg = tanh_ap(v1.x);                                                 \
    float og = fmaf(0.5f, tanh_ap(v1.y), 0.5f);                               \
    c = fmaf(fg, c, ig * gg);                                                 \
    h = og * tanh_ap(c);                                                      \
    if (valid) out[(TT) * STRIDE + base_idx] = h;                             \
} while (0)

// ---------------------------------------------------------------------------
// Fused kernel: warps 0-3 produce gates via mma.sync bf16 (2-part split);
// warps 4-7 run the packed recurrence (unchanged from R12).
// ---------------------------------------------------------------------------
__global__ __launch_bounds__(256, 1) void lstm_fused_kernel(
    const float* __restrict__ x,    const float* __restrict__ h_in,
    const float* __restrict__ c_in, const float* __restrict__ Wih,
    const float* __restrict__ Whh,  const float* __restrict__ bih,
    const float* __restrict__ bhh,  float* __restrict__ out)
{
    __shared__ float4 gbuf[2][CH][EPB * NH];          // gate ring: 18432 B
    __shared__ __align__(16) unsigned char tiles[TILES_BYTES];
    __shared__ int ready, done;

    const int tid  = threadIdx.x;
    const int w    = tid >> 5;
    const int lane = tid & 31;
    const int b0   = blockIdx.x * EPB;
    const unsigned tb = smem_u32(tiles);

    // zero the bf16 tile region (covers all padding rows/cols)
    for (int i = tid; i < TILES_BYTES / 16; i += 256) sts_zero4(tb + i * 16);
    if (tid == 0) { ready = 0; done = 0; }
    __syncthreads();

    // ---- stage B (weights + bias col), once. Row n = j*4+g; k 0..42. ----
    for (int i = tid; i < 36 * 43; i += 256) {
        int n = i / 43, k = i - 43 * n;
        int j = n >> 2, g = n & 3;
        float sc = (g == 2) ? 1.0f : 0.5f;
        float v = (k < 42) ? Wih[(g * NH + j) * NIN + k] * sc
                           : (bih[g * NH + j] + bhh[g * NH + j]) * sc;
        unsigned hb = f2bf(v);
        unsigned lb = f2bf(v - bf2f(hb));
        *(unsigned short*)(tiles + BH_O + n * 112 + k * 2) = (unsigned short)hb;
        *(unsigned short*)(tiles + BL_O + n * 112 + k * 2) = (unsigned short)lb;
    }
    __syncthreads();

    if (w >= EPB) {
        // ====================== COMPUTE WARP (wid 4-7, 1 elem) ===============
        const int cw = w - EPB;
        const int b  = b0 + cw;
        const int j  = (lane < 9) ? lane : 8;
        const bool valid = (lane < 9);

        ull W01[NH], W23[NH];
        #pragma unroll
        for (int k = 0; k < NH; k++) {
            W01[k] = pack2(0.5f * Whh[(0 * NH + j) * NH + k],
                           0.5f * Whh[(1 * NH + j) * NH + k]);
            W23[k] = pack2(       Whh[(2 * NH + j) * NH + k],
                           0.5f * Whh[(3 * NH + j) * NH + k]);
        }
        float h = h_in[b * NH + j];
        float c = c_in[b * NH + j];
        const int base_idx = b * NH + j;
        const int u = cw * NH + j;

        for (int cch = 0; cch < NCH; cch++) {
            const int buf = cch & 1;
            const int t0  = cch * CH;
            if (ld_acq_sh(&ready) < cch + 1) {
                while (ld_acq_sh(&ready) < cch + 1) __nanosleep(32);
            }
            const float4* xb = &gbuf[buf][0][u];
            ull p01, p23, n01, n23;
            lds_v2u64(p01, p23, xb);
            #pragma unroll
            for (int s = 0; s < CH; s++) {
                if (s + 1 < CH) lds_v2u64(n01, n23, xb + (s + 1) * (EPB * NH));
                LSTM_STEP_P(p01, p23, t0 + s);
                p01 = n01; p23 = n23;
            }
            __syncwarp();
            if (lane == 0) red_rel_sh(&done, 1);
        }

        if (valid) {
            out[(size_t)T_LEN * STRIDE + base_idx]          = h;  // hn
            out[(size_t)T_LEN * STRIDE + STRIDE + base_idx] = c;  // cn
        }
    } else {
        // ====================== PRODUCER WARP (wid 0-3) ======================
        // mma tiling: warp w owns 16 chunk-rows [w*16, w*16+16); computes all
        // 5 n-tiles (N=40) over 3 k-tiles (K=48) x 3 split terms.
        // Staging roles: row sr = tid>>1 (0..63), part sp = tid&1.
        const int sr = tid >> 1;
        const int sp = tid & 1;
        const int k2b = sp ? 11 : 0;
        const int k2n = sp ? 10 : 11;
        const float2* xsrc0 = (const float2*)
            (x + ((size_t)(sr >> 2) * B_SZ + (b0 + (sr & 3))) * NIN) + k2b;
        const size_t chstep = (size_t)CH * B_SZ * NIN / 2;

        const int g   = lane >> 2;          // fragment group row
        const int tig = lane & 3;           // thread-in-group

        // frag base addresses (conflict-free: 112B pitch)
        const unsigned abase  = tb + AH_O + (w * 16 + g) * 112 + tig * 4;
        const unsigned albase = abase + (AL_O - AH_O);

        // ---- prologue: stage A chunk 0 ----
        {
            float2 xr[11];
            #pragma unroll
            for (int q = 0; q < 11; q++) if (q < k2n) xr[q] = xsrc0[q];
            #pragma unroll
            for (int q = 0; q < 11; q++) {
                if (q < k2n) {
                    unsigned h0 = f2bf(xr[q].x), h1 = f2bf(xr[q].y);
                    unsigned l0 = f2bf(xr[q].x - bf2f(h0));
                    unsigned l1 = f2bf(xr[q].y - bf2f(h1));
                    *(unsigned*)(tiles + AH_O + sr * 112 + (k2b + q) * 4) = (h1 << 16) | h0;
                    *(unsigned*)(tiles + AL_O + sr * 112 + (k2b + q) * 4) = (l1 << 16) | l0;
                }
            }
            if (sp == 0) {
                *(unsigned*)(tiles + AH_O + sr * 112 + 84) = 0x00003F80u; // bias col = 1.0
                *(unsigned*)(tiles + AL_O + sr * 112 + 84) = 0u;
            }
            asm volatile("bar.sync 1, 128;" ::: "memory");
        }

        for (int cch = 0; cch < NCH; cch++) {
            const int buf = cch & 1;

            // prefetch next chunk's x (LDG overlaps mma mainloop)
            float2 xr[11];
            if (cch + 1 < NCH) {
                const float2* src = xsrc0 + (size_t)(cch + 1) * chstep;
                #pragma unroll
                for (int q = 0; q < 11; q++) if (q < k2n) xr[q] = src[q];
            }

            // gbuf slot free? (lag-2 ring)
            if (cch >= 2) {
                const int need = EPB * (cch - 1);
                if (ld_vol_sh(&done) < need) {
                    while (ld_vol_sh(&done) < need) __nanosleep(64);
                }
            }

            // ---- load A fragments (hi & lo) for this warp's 16 rows ----
            unsigned ah[3][4], al[3][4];
            #pragma unroll
            for (int kt = 0; kt < 3; kt++) {
                ah[kt][0] = lds_b32(abase  + kt * 32);
                ah[kt][1] = lds_b32(abase  + kt * 32 + 896);
                ah[kt][2] = lds_b32(abase  + kt * 32 + 16);
                ah[kt][3] = lds_b32(abase  + kt * 32 + 912);
                al[kt][0] = lds_b32(albase + kt * 32);
                al[kt][1] = lds_b32(albase + kt * 32 + 896);
                al[kt][2] = lds_b32(albase + kt * 32 + 16);
                al[kt][3] = lds_b32(albase + kt * 32 + 912);
            }

            // ---- mma over 5 n-tiles, 3 k-tiles, 3 split terms ----
            #pragma unroll
            for (int nt = 0; nt < 5; nt++) {
                float d0 = 0.f, d1 = 0.f, d2 = 0.f, d3 = 0.f;
                const unsigned bhb = tb + BH_O + (nt * 8 + g) * 112 + tig * 4;
                const unsigned blb = bhb + (BL_O - BH_O);
                #pragma unroll
                for (int kt = 0; kt < 3; kt++) {
                    unsigned bh0 = lds_b32(bhb + kt * 32);
                    unsigned bh1 = lds_b32(bhb + kt * 32 + 16);
                    unsigned bl0 = lds_b32(blb + kt * 32);
                    unsigned bl1 = lds_b32(blb + kt * 32 + 16);
                    mma_bf16(d0, d1, d2, d3, ah[kt][0], ah[kt][1], ah[kt][2], ah[kt][3], bh0, bh1);
                    mma_bf16(d0, d1, d2, d3, ah[kt][0], ah[kt][1], ah[kt][2], ah[kt][3], bl0, bl1);
                    mma_bf16(d0, d1, d2, d3, al[kt][0], al[kt][1], al[kt][2], al[kt][3], bh0, bh1);
                }
                // ---- scatter D pairs into the gate ring ----
                const int n0 = nt * 8 + 2 * tig;
                if (n0 < 36) {
                    const int j  = n0 >> 2;
                    const int hs = (n0 & 3) >> 1;
                    const int r0 = w * 16 + g;
                    const int r1 = r0 + 8;
                    float2* p0 = (float2*)&gbuf[buf][r0 >> 2][(r0 & 3) * NH + j] + hs;
                    float2* p1 = (float2*)&gbuf[buf][r1 >> 2][(r1 & 3) * NH + j] + hs;
                    *p0 = make_float2(d0, d1);
                    *p1 = make_float2(d2, d3);
                }
            }

            asm volatile("bar.sync 1, 128;" ::: "memory");
            if (tid == 0) st_rel_sh(&ready, cch + 1);

            // ---- stage next chunk's A from registers ----
            if (cch + 1 < NCH) {
                #pragma unroll
                for (int q = 0; q < 11; q++) {
                    if (q < k2n) {
                        unsigned h0 = f2bf(xr[q].x), h1 = f2bf(xr[q].y);
                        unsigned l0 = f2bf(xr[q].x - bf2f(h0));
                        unsigned l1 = f2bf(xr[q].y - bf2f(h1));
                        *(unsigned*)(tiles + AH_O + sr * 112 + (k2b + q) * 4) = (h1 << 16) | h0;
                        *(unsigned*)(tiles + AL_O + sr * 112 + (k2b + q) * 4) = (l1 << 16) | l0;
                    }
                }
                if (sp == 0) {
                    *(unsigned*)(tiles + AH_O + sr * 112 + 84) = 0x00003F80u;
                    *(unsigned*)(tiles + AL_O + sr * 112 + 84) = 0u;
                }
                asm volatile("bar.sync 1, 128;" ::: "memory");
            }
        }
    }
}

// ---------------------------------------------------------------------------
extern "C" void kernel_launch(void* const* d_in, const int* in_sizes, int n_in,
                              void* d_out, int out_size) {
    const float* x   = (const float*)d_in[0];
    const float* h   = (const float*)d_in[1];
    const float* c   = (const float*)d_in[2];
    const float* Wih = (const float*)d_in[3];
    const float* Whh = (const float*)d_in[4];
    const float* bih = (const float*)d_in[5];
    const float* bhh = (const float*)d_in[6];
    float* out = (float*)d_out;

    lstm_fused_kernel<<<NBLK, 256>>>(x, h, c, Wih, Whh, bih, bhh, out);
}

// round 16
// speedup vs baseline: 1.2783x; 1.0842x over previous
#include <cuda_runtime.h>
#include <cstdint>

#define T_LEN 4096
#define B_SZ  512
#define NIN   42
#define NH    9
#define STRIDE (B_SZ * NH)   // 4608 floats per timestep (output)
#define EPB   4              // batch elements per block
#define NBLK  (B_SZ / EPB)   // 128 blocks
#define CH    16             // timesteps per chunk
#define NCH   (T_LEN / CH)   // 256

// bf16 tile region (112-byte row pitch, conflict-free for frag loads)
#define AH_O  0              // A hi: 64 x 56 bf16 (7168 B)
#define AL_O  7168           // A lo
#define BH_O  14336          // B hi: 40 x 56 bf16 (4480 B)
#define BL_O  18816          // B lo
#define TILES_BYTES 23296

typedef unsigned long long ull;

// ---------------------------------------------------------------------------
// helpers
// ---------------------------------------------------------------------------
__device__ __forceinline__ ull ffma2(ull a, ull b, ull c) {
    ull d;
    asm("fma.rn.f32x2 %0, %1, %2, %3;" : "=l"(d) : "l"(a), "l"(b), "l"(c));
    return d;
}
__device__ __forceinline__ ull fadd2(ull a, ull b) {
    ull d;
    asm("add.rn.f32x2 %0, %1, %2;" : "=l"(d) : "l"(a), "l"(b));
    return d;
}
__device__ __forceinline__ ull pack2(float a, float b) {
    ull r;
    asm("mov.b64 %0, {%1,%2};" : "=l"(r) : "f"(a), "f"(b));
    return r;
}
__device__ __forceinline__ void lds_v2u64(ull& a, ull& b, const void* p) {
    unsigned addr = (unsigned)__cvta_generic_to_shared(p);
    asm volatile("ld.shared.v2.u64 {%0,%1}, [%2];" : "=l"(a), "=l"(b) : "r"(addr));
}
__device__ __forceinline__ unsigned lds_b32(unsigned addr) {
    unsigned v;
    asm volatile("ld.shared.b32 %0, [%1];" : "=r"(v) : "r"(addr));
    return v;
}
__device__ __forceinline__ float2 unpack2(ull v) {
    float2 f;
    f.x = __uint_as_float((unsigned)(v & 0xffffffffull));
    f.y = __uint_as_float((unsigned)(v >> 32));
    return f;
}
__device__ __forceinline__ float tanh_ap(float x) {
    float y;
    asm("tanh.approx.f32 %0, %1;" : "=f"(y) : "f"(x));
    return y;
}
__device__ __forceinline__ int ld_acq_sh(const int* p) {
    unsigned a = (unsigned)__cvta_generic_to_shared(p);
    int v;
    asm volatile("ld.acquire.cta.shared.b32 %0, [%1];" : "=r"(v) : "r"(a));
    return v;
}
__device__ __forceinline__ int ld_vol_sh(const int* p) {
    unsigned a = (unsigned)__cvta_generic_to_shared(p);
    int v;
    asm volatile("ld.volatile.shared.b32 %0, [%1];" : "=r"(v) : "r"(a));
    return v;
}
__device__ __forceinline__ void st_rel_sh(int* p, int v) {
    unsigned a = (unsigned)__cvta_generic_to_shared(p);
    asm volatile("st.release.cta.shared.b32 [%0], %1;" :: "r"(a), "r"(v) : "memory");
}
__device__ __forceinline__ void red_rel_sh(int* p, int v) {
    unsigned a = (unsigned)__cvta_generic_to_shared(p);
    asm volatile("red.release.cta.shared.add.u32 [%0], %1;" :: "r"(a), "r"(v) : "memory");
}
__device__ __forceinline__ void sts_zero4(unsigned addr) {
    asm volatile("st.shared.v4.b32 [%0], {%1,%1,%1,%1};" :: "r"(addr), "r"(0) : "memory");
}
__device__ __forceinline__ unsigned smem_u32(const void* p) {
    return (unsigned)__cvta_generic_to_shared(p);
}
// bf16 round-to-nearest-even from fp32 bits (scalar, staging-B only)
__device__ __forceinline__ unsigned f2bf(float v) {
    unsigned u = __float_as_uint(v);
    return (u + 0x7FFFu + ((u >> 16) & 1u)) >> 16;
}
__device__ __forceinline__ float bf2f(unsigned b) {
    return __uint_as_float(b << 16);
}
// packed bf16x2 convert: result = (bf(hi_f) << 16) | bf(lo_f)
__device__ __forceinline__ unsigned cvt_bf16x2(float hi_f, float lo_f) {
    unsigned r;
    asm("cvt.rn.bf16x2.f32 %0, %1, %2;" : "=r"(r) : "f"(hi_f), "f"(lo_f));
    return r;
}
__device__ __forceinline__ void mma_bf16(float& d0, float& d1, float& d2, float& d3,
                                         unsigned a0, unsigned a1, unsigned a2, unsigned a3,
                                         unsigned b0, unsigned b1) {
    asm volatile(
        "mma.sync.aligned.m16n8k16.row.col.f32.bf16.bf16.f32 "
        "{%0,%1,%2,%3}, {%4,%5,%6,%7}, {%8,%9}, {%0,%1,%2,%3};"
        : "+f"(d0), "+f"(d1), "+f"(d2), "+f"(d3)
        : "r"(a0), "r"(a1), "r"(a2), "r"(a3), "r"(b0), "r"(b1));
}

// Packed compute step with SPLIT accumulator chains (k 0-4 / k 5-8).
// P01=(i/2,f/2), P23=(g,o/2); biases folded upstream.
#define LSTM_STEP_P(P01, P23, TT) do {                                        \
    ull a01 = (P01), a23 = (P23);                                             \
    ull e01 = 0ull, e23 = 0ull;                                               \
    _Pragma("unroll")                                                         \
    for (int k = 0; k < 9; k++) {                                             \
        float hk = __shfl_sync(0xFFFFFFFFu, h, k);                            \
        ull hh = pack2(hk, hk);                                               \
        if (k < 5) {                                                          \
            a01 = ffma2(W01[k], hh, a01);                                     \
            a23 = ffma2(W23[k], hh, a23);                                     \
        } else {                                                              \
            e01 = ffma2(W01[k], hh, e01);                                     \
            e23 = ffma2(W23[k], hh, e23);                                     \
        }                                                                     \
    }                                                                         \
    a01 = fadd2(a01, e01);                                                    \
    a23 = fadd2(a23, e23);                                                    \
    float2 v0 = unpack2(a01);                                                 \
    float2 v1 = unpack2(a23);                                                 \
    float ig = fmaf(0.5f, tanh_ap(v0.x), 0.5f);                               \
    float fg = fmaf(0.5f, tanh_ap(v0.y), 0.5f);                               \
    float gg = tanh_ap(v1.x);                                                 \
    float og = fmaf(0.5f, tanh_ap(v1.y), 0.5f);                               \
    c = fmaf(fg, c, ig * gg);                                                 \
    h = og * tanh_ap(c);                                                      \
    if (valid) out[(TT) * STRIDE + base_idx] = h;                             \
} while (0)

// ---------------------------------------------------------------------------
// Fused kernel: warps 0-3 produce gates via mma.sync bf16 (B frags hoisted to
// registers); warps 4-7 run the packed split-chain recurrence.
// ---------------------------------------------------------------------------
__global__ __launch_bounds__(256, 1) void lstm_fused_kernel(
    const float* __restrict__ x,    const float* __restrict__ h_in,
    const float* __restrict__ c_in, const float* __restrict__ Wih,
    const float* __restrict__ Whh,  const float* __restrict__ bih,
    const float* __restrict__ bhh,  float* __restrict__ out)
{
    __shared__ float4 gbuf[2][CH][EPB * NH];          // gate ring: 18432 B
    __shared__ __align__(16) unsigned char tiles[TILES_BYTES];
    __shared__ int ready, done;

    const int tid  = threadIdx.x;
    const int w    = tid >> 5;
    const int lane = tid & 31;
    const int b0   = blockIdx.x * EPB;
    const unsigned tb = smem_u32(tiles);

    // zero the bf16 tile region (covers all padding rows/cols)
    for (int i = tid; i < TILES_BYTES / 16; i += 256) sts_zero4(tb + i * 16);
    if (tid == 0) { ready = 0; done = 0; }
    __syncthreads();

    // ---- stage B (weights + bias col), once. Row n = j*4+g; k 0..42. ----
    for (int i = tid; i < 36 * 43; i += 256) {
        int n = i / 43, k = i - 43 * n;
        int j = n >> 2, g = n & 3;
        float sc = (g == 2) ? 1.0f : 0.5f;
        float v = (k < 42) ? Wih[(g * NH + j) * NIN + k] * sc
                           : (bih[g * NH + j] + bhh[g * NH + j]) * sc;
        unsigned hb = f2bf(v);
        unsigned lb = f2bf(v - bf2f(hb));
        *(unsigned short*)(tiles + BH_O + n * 112 + k * 2) = (unsigned short)hb;
        *(unsigned short*)(tiles + BL_O + n * 112 + k * 2) = (unsigned short)lb;
    }
    __syncthreads();

    if (w >= EPB) {
        // ====================== COMPUTE WARP (wid 4-7, 1 elem) ===============
        const int cw = w - EPB;
        const int b  = b0 + cw;
        const int j  = (lane < 9) ? lane : 8;
        const bool valid = (lane < 9);

        ull W01[NH], W23[NH];
        #pragma unroll
        for (int k = 0; k < NH; k++) {
            W01[k] = pack2(0.5f * Whh[(0 * NH + j) * NH + k],
                           0.5f * Whh[(1 * NH + j) * NH + k]);
            W23[k] = pack2(       Whh[(2 * NH + j) * NH + k],
                           0.5f * Whh[(3 * NH + j) * NH + k]);
        }
        float h = h_in[b * NH + j];
        float c = c_in[b * NH + j];
        const int base_idx = b * NH + j;
        const int u = cw * NH + j;

        for (int cch = 0; cch < NCH; cch++) {
            const int buf = cch & 1;
            const int t0  = cch * CH;
            if (ld_acq_sh(&ready) < cch + 1) {
                while (ld_acq_sh(&ready) < cch + 1) __nanosleep(32);
            }
            const float4* xb = &gbuf[buf][0][u];
            // 2-deep software pipeline on gate loads
            ull p01, p23, q01, q23, n01, n23;
            lds_v2u64(p01, p23, xb);
            lds_v2u64(q01, q23, xb + (EPB * NH));
            #pragma unroll
            for (int s = 0; s < CH; s++) {
                if (s + 2 < CH) lds_v2u64(n01, n23, xb + (s + 2) * (EPB * NH));
                LSTM_STEP_P(p01, p23, t0 + s);
                p01 = q01; p23 = q23;
                q01 = n01; q23 = n23;
            }
            __syncwarp();
            if (lane == 0) red_rel_sh(&done, 1);
        }

        if (valid) {
            out[(size_t)T_LEN * STRIDE + base_idx]          = h;  // hn
            out[(size_t)T_LEN * STRIDE + STRIDE + base_idx] = c;  // cn
        }
    } else {
        // ====================== PRODUCER WARP (wid 0-3) ======================
        // Warp w owns 16 chunk-rows [w*16, w*16+16); 5 n-tiles x 3 k-tiles x
        // 3 split terms. B fragments hoisted to registers (loop-invariant).
        const int sr = tid >> 1;
        const int sp = tid & 1;
        const int k2b = sp ? 11 : 0;
        const int k2n = sp ? 10 : 11;
        const float2* xsrc0 = (const float2*)
            (x + ((size_t)(sr >> 2) * B_SZ + (b0 + (sr & 3))) * NIN) + k2b;
        const size_t chstep = (size_t)CH * B_SZ * NIN / 2;

        const int g   = lane >> 2;          // fragment group row
        const int tig = lane & 3;           // thread-in-group

        const unsigned abase  = tb + AH_O + (w * 16 + g) * 112 + tig * 4;
        const unsigned albase = abase + (AL_O - AH_O);

        // ---- hoist B fragments (hi & lo) into registers, once ----
        unsigned bh0[5][3], bh1[5][3], bl0[5][3], bl1[5][3];
        #pragma unroll
        for (int nt = 0; nt < 5; nt++) {
            const unsigned bhb = tb + BH_O + (nt * 8 + g) * 112 + tig * 4;
            const unsigned blb = bhb + (BL_O - BH_O);
            #pragma unroll
            for (int kt = 0; kt < 3; kt++) {
                bh0[nt][kt] = lds_b32(bhb + kt * 32);
                bh1[nt][kt] = lds_b32(bhb + kt * 32 + 16);
                bl0[nt][kt] = lds_b32(blb + kt * 32);
                bl1[nt][kt] = lds_b32(blb + kt * 32 + 16);
            }
        }

        // ---- prologue: stage A chunk 0 ----
        {
            float2 xr[11];
            #pragma unroll
            for (int q = 0; q < 11; q++) if (q < k2n) xr[q] = xsrc0[q];
            #pragma unroll
            for (int q = 0; q < 11; q++) {
                if (q < k2n) {
                    unsigned hp = cvt_bf16x2(xr[q].y, xr[q].x);
                    float l0 = xr[q].x - __uint_as_float(hp << 16);
                    float l1 = xr[q].y - __uint_as_float(hp & 0xFFFF0000u);
                    unsigned lp = cvt_bf16x2(l1, l0);
                    *(unsigned*)(tiles + AH_O + sr * 112 + (k2b + q) * 4) = hp;
                    *(unsigned*)(tiles + AL_O + sr * 112 + (k2b + q) * 4) = lp;
                }
            }
            if (sp == 0) {
                *(unsigned*)(tiles + AH_O + sr * 112 + 84) = 0x00003F80u; // bias col = 1.0
                *(unsigned*)(tiles + AL_O + sr * 112 + 84) = 0u;
            }
            asm volatile("bar.sync 1, 128;" ::: "memory");
        }

        for (int cch = 0; cch < NCH; cch++) {
            const int buf = cch & 1;

            // prefetch next chunk's x (LDG overlaps mma mainloop)
            float2 xr[11];
            if (cch + 1 < NCH) {
                const float2* src = xsrc0 + (size_t)(cch + 1) * chstep;
                #pragma unroll
                for (int q = 0; q < 11; q++) if (q < k2n) xr[q] = src[q];
            }

            // gbuf slot free? (lag-2 ring)
            if (cch >= 2) {
                const int need = EPB * (cch - 1);
                if (ld_vol_sh(&done) < need) {
                    while (ld_vol_sh(&done) < need) __nanosleep(64);
                }
            }

            // ---- load A fragments (hi & lo) for this warp's 16 rows ----
            unsigned ah[3][4], al[3][4];
            #pragma unroll
            for (int kt = 0; kt < 3; kt++) {
                ah[kt][0] = lds_b32(abase  + kt * 32);
                ah[kt][1] = lds_b32(abase  + kt * 32 + 896);
                ah[kt][2] = lds_b32(abase  + kt * 32 + 16);
                ah[kt][3] = lds_b32(abase  + kt * 32 + 912);
                al[kt][0] = lds_b32(albase + kt * 32);
                al[kt][1] = lds_b32(albase + kt * 32 + 896);
                al[kt][2] = lds_b32(albase + kt * 32 + 16);
                al[kt][3] = lds_b32(albase + kt * 32 + 912);
            }

            // ---- mma over 5 n-tiles, 3 k-tiles, 3 split terms ----
            #pragma unroll
            for (int nt = 0; nt < 5; nt++) {
                float d0 = 0.f, d1 = 0.f, d2 = 0.f, d3 = 0.f;
                #pragma unroll
                for (int kt = 0; kt < 3; kt++) {
                    mma_bf16(d0, d1, d2, d3,
                             ah[kt][0], ah[kt][1], ah[kt][2], ah[kt][3],
                             bh0[nt][kt], bh1[nt][kt]);
                    mma_bf16(d0, d1, d2, d3,
                             ah[kt][0], ah[kt][1], ah[kt][2], ah[kt][3],
                             bl0[nt][kt], bl1[nt][kt]);
                    mma_bf16(d0, d1, d2, d3,
                             al[kt][0], al[kt][1], al[kt][2], al[kt][3],
                             bh0[nt][kt], bh1[nt][kt]);
                }
                // ---- scatter D pairs into the gate ring ----
                const int n0 = nt * 8 + 2 * tig;
                if (n0 < 36) {
                    const int j  = n0 >> 2;
                    const int hs = (n0 & 3) >> 1;
                    const int r0 = w * 16 + g;
                    const int r1 = r0 + 8;
                    float2* p0 = (float2*)&gbuf[buf][r0 >> 2][(r0 & 3) * NH + j] + hs;
                    float2* p1 = (float2*)&gbuf[buf][r1 >> 2][(r1 & 3) * NH + j] + hs;
                    *p0 = make_float2(d0, d1);
                    *p1 = make_float2(d2, d3);
                }
            }

            asm volatile("bar.sync 1, 128;" ::: "memory");
            if (tid == 0) st_rel_sh(&ready, cch + 1);

            // ---- stage next chunk's A from registers ----
            if (cch + 1 < NCH) {
                #pragma unroll
                for (int q = 0; q < 11; q++) {
                    if (q < k2n) {
                        unsigned hp = cvt_bf16x2(xr[q].y, xr[q].x);
                        float l0 = xr[q].x - __uint_as_float(hp << 16);
                        float l1 = xr[q].y - __uint_as_float(hp & 0xFFFF0000u);
                        unsigned lp = cvt_bf16x2(l1, l0);
                        *(unsigned*)(tiles + AH_O + sr * 112 + (k2b + q) * 4) = hp;
                        *(unsigned*)(tiles + AL_O + sr * 112 + (k2b + q) * 4) = lp;
                    }
                }
                if (sp == 0) {
                    *(unsigned*)(tiles + AH_O + sr * 112 + 84) = 0x00003F80u;
                    *(unsigned*)(tiles + AL_O + sr * 112 + 84) = 0u;
                }
                asm volatile("bar.sync 1, 128;" ::: "memory");
            }
        }
    }
}

// ---------------------------------------------------------------------------
extern "C" void kernel_launch(void* const* d_in, const int* in_sizes, int n_in,
                              void* d_out, int out_size) {
    const float* x   = (const float*)d_in[0];
    const float* h   = (const float*)d_in[1];
    const float* c   = (const float*)d_in[2];
    const float* Wih = (const float*)d_in[3];
    const float* Whh = (const float*)d_in[4];
    const float* bih = (const float*)d_in[5];
    const float* bhh = (const float*)d_in[6];
    float* out = (float*)d_out;

    lstm_fused_kernel<<<NBLK, 256>>>(x, h, c, Wih, Whh, bih, bhh, out);
}

// round 17
// speedup vs baseline: 1.2795x; 1.0009x over previous
#include <cuda_runtime.h>
#include <cstdint>

#define T_LEN 4096
#define B_SZ  512
#define NIN   42
#define NH    9
#define STRIDE (B_SZ * NH)   // 4608 floats per timestep (output)
#define EPB   4              // batch elements per block
#define NBLK  (B_SZ / EPB)   // 128 blocks
#define CH    16             // timesteps per chunk
#define NCH   (T_LEN / CH)   // 256

// bf16 tile region (112-byte row pitch, conflict-free for frag loads)
#define AH_O  0              // A hi: 64 x 56 bf16 (7168 B)
#define AL_O  7168           // A lo
#define BH_O  14336          // B hi: 40 x 56 bf16 (4480 B)
#define BL_O  18816          // B lo
#define TILES_BYTES 23296

typedef unsigned long long ull;

// ---------------------------------------------------------------------------
// helpers
// ---------------------------------------------------------------------------
__device__ __forceinline__ ull ffma2(ull a, ull b, ull c) {
    ull d;
    asm("fma.rn.f32x2 %0, %1, %2, %3;" : "=l"(d) : "l"(a), "l"(b), "l"(c));
    return d;
}
__device__ __forceinline__ ull fadd2(ull a, ull b) {
    ull d;
    asm("add.rn.f32x2 %0, %1, %2;" : "=l"(d) : "l"(a), "l"(b));
    return d;
}
__device__ __forceinline__ ull pack2(float a, float b) {
    ull r;
    asm("mov.b64 %0, {%1,%2};" : "=l"(r) : "f"(a), "f"(b));
    return r;
}
__device__ __forceinline__ void lds_v2u64(ull& a, ull& b, const void* p) {
    unsigned addr = (unsigned)__cvta_generic_to_shared(p);
    asm volatile("ld.shared.v2.u64 {%0,%1}, [%2];" : "=l"(a), "=l"(b) : "r"(addr));
}
__device__ __forceinline__ unsigned lds_b32(unsigned addr) {
    unsigned v;
    asm volatile("ld.shared.b32 %0, [%1];" : "=r"(v) : "r"(addr));
    return v;
}
__device__ __forceinline__ float2 unpack2(ull v) {
    float2 f;
    f.x = __uint_as_float((unsigned)(v & 0xffffffffull));
    f.y = __uint_as_float((unsigned)(v >> 32));
    return f;
}
__device__ __forceinline__ float tanh_ap(float x) {
    float y;
    asm("tanh.approx.f32 %0, %1;" : "=f"(y) : "f"(x));
    return y;
}
__device__ __forceinline__ int ld_acq_sh(const int* p) {
    unsigned a = (unsigned)__cvta_generic_to_shared(p);
    int v;
    asm volatile("ld.acquire.cta.shared.b32 %0, [%1];" : "=r"(v) : "r"(a));
    return v;
}
__device__ __forceinline__ int ld_vol_sh(const int* p) {
    unsigned a = (unsigned)__cvta_generic_to_shared(p);
    int v;
    asm volatile("ld.volatile.shared.b32 %0, [%1];" : "=r"(v) : "r"(a));
    return v;
}
__device__ __forceinline__ void st_rel_sh(int* p, int v) {
    unsigned a = (unsigned)__cvta_generic_to_shared(p);
    asm volatile("st.release.cta.shared.b32 [%0], %1;" :: "r"(a), "r"(v) : "memory");
}
__device__ __forceinline__ void red_rel_sh(int* p, int v) {
    unsigned a = (unsigned)__cvta_generic_to_shared(p);
    asm volatile("red.release.cta.shared.add.u32 [%0], %1;" :: "r"(a), "r"(v) : "memory");
}
__device__ __forceinline__ void sts_zero4(unsigned addr) {
    asm volatile("st.shared.v4.b32 [%0], {%1,%1,%1,%1};" :: "r"(addr), "r"(0) : "memory");
}
__device__ __forceinline__ unsigned smem_u32(const void* p) {
    return (unsigned)__cvta_generic_to_shared(p);
}
// bf16 round-to-nearest-even from fp32 bits (scalar, staging-B only)
__device__ __forceinline__ unsigned f2bf(float v) {
    unsigned u = __float_as_uint(v);
    return (u + 0x7FFFu + ((u >> 16) & 1u)) >> 16;
}
__device__ __forceinline__ float bf2f(unsigned b) {
    return __uint_as_float(b << 16);
}
// packed bf16x2 convert: result = (bf(hi_f) << 16) | bf(lo_f)
__device__ __forceinline__ unsigned cvt_bf16x2(float hi_f, float lo_f) {
    unsigned r;
    asm("cvt.rn.bf16x2.f32 %0, %1, %2;" : "=r"(r) : "f"(hi_f), "f"(lo_f));
    return r;
}
__device__ __forceinline__ void mma_bf16(float& d0, float& d1, float& d2, float& d3,
                                         unsigned a0, unsigned a1, unsigned a2, unsigned a3,
                                         unsigned b0, unsigned b1) {
    asm volatile(
        "mma.sync.aligned.m16n8k16.row.col.f32.bf16.bf16.f32 "
        "{%0,%1,%2,%3}, {%4,%5,%6,%7}, {%8,%9}, {%0,%1,%2,%3};"
        : "+f"(d0), "+f"(d1), "+f"(d2), "+f"(d3)
        : "r"(a0), "r"(a1), "r"(a2), "r"(a3), "r"(b0), "r"(b1));
}

// Packed compute step with SPLIT accumulator chains (k 0-4 / k 5-8).
// P01=(i/2,f/2), P23=(g,o/2); biases folded upstream.
#define LSTM_STEP_P(P01, P23, TT) do {                                        \
    ull a01 = (P01), a23 = (P23);                                             \
    ull e01 = 0ull, e23 = 0ull;                                               \
    _Pragma("unroll")                                                         \
    for (int k = 0; k < 9; k++) {                                             \
        float hk = __shfl_sync(0xFFFFFFFFu, h, k);                            \
        ull hh = pack2(hk, hk);                                               \
        if (k < 5) {                                                          \
            a01 = ffma2(W01[k], hh, a01);                                     \
            a23 = ffma2(W23[k], hh, a23);                                     \
        } else {                                                              \
            e01 = ffma2(W01[k], hh, e01);                                     \
            e23 = ffma2(W23[k], hh, e23);                                     \
        }                                                                     \
    }                                                                         \
    a01 = fadd2(a01, e01);                                                    \
    a23 = fadd2(a23, e23);                                                    \
    float2 v0 = unpack2(a01);                                                 \
    float2 v1 = unpack2(a23);                                                 \
    float ig = fmaf(0.5f, tanh_ap(v0.x), 0.5f);                               \
    float fg = fmaf(0.5f, tanh_ap(v0.y), 0.5f);                               \
    float gg = tanh_ap(v1.x);                                                 \
    float og = fmaf(0.5f, tanh_ap(v1.y), 0.5f);                               \
    c = fmaf(fg, c, ig * gg);                                                 \
    h = og * tanh_ap(c);                                                      \
    if (valid) out[(TT) * STRIDE + base_idx] = h;                             \
} while (0)

// ---------------------------------------------------------------------------
// Fused kernel: warps 0-3 produce gates via mma.sync bf16 (B frags hoisted to
// registers); warps 4-7 run the packed split-chain recurrence.
// ---------------------------------------------------------------------------
__global__ __launch_bounds__(256, 1) void lstm_fused_kernel(
    const float* __restrict__ x,    const float* __restrict__ h_in,
    const float* __restrict__ c_in, const float* __restrict__ Wih,
    const float* __restrict__ Whh,  const float* __restrict__ bih,
    const float* __restrict__ bhh,  float* __restrict__ out)
{
    __shared__ float4 gbuf[2][CH][EPB * NH];          // gate ring: 18432 B
    __shared__ __align__(16) unsigned char tiles[TILES_BYTES];
    __shared__ int ready, done;

    const int tid  = threadIdx.x;
    const int w    = tid >> 5;
    const int lane = tid & 31;
    const int b0   = blockIdx.x * EPB;
    const unsigned tb = smem_u32(tiles);

    // zero the bf16 tile region (covers all padding rows/cols)
    for (int i = tid; i < TILES_BYTES / 16; i += 256) sts_zero4(tb + i * 16);
    if (tid == 0) { ready = 0; done = 0; }
    __syncthreads();

    // ---- stage B (weights + bias col), once. Row n = j*4+g; k 0..42. ----
    for (int i = tid; i < 36 * 43; i += 256) {
        int n = i / 43, k = i - 43 * n;
        int j = n >> 2, g = n & 3;
        float sc = (g == 2) ? 1.0f : 0.5f;
        float v = (k < 42) ? Wih[(g * NH + j) * NIN + k] * sc
                           : (bih[g * NH + j] + bhh[g * NH + j]) * sc;
        unsigned hb = f2bf(v);
        unsigned lb = f2bf(v - bf2f(hb));
        *(unsigned short*)(tiles + BH_O + n * 112 + k * 2) = (unsigned short)hb;
        *(unsigned short*)(tiles + BL_O + n * 112 + k * 2) = (unsigned short)lb;
    }
    __syncthreads();

    if (w >= EPB) {
        // ====================== COMPUTE WARP (wid 4-7, 1 elem) ===============
        const int cw = w - EPB;
        const int b  = b0 + cw;
        const int j  = (lane < 9) ? lane : 8;
        const bool valid = (lane < 9);

        ull W01[NH], W23[NH];
        #pragma unroll
        for (int k = 0; k < NH; k++) {
            W01[k] = pack2(0.5f * Whh[(0 * NH + j) * NH + k],
                           0.5f * Whh[(1 * NH + j) * NH + k]);
            W23[k] = pack2(       Whh[(2 * NH + j) * NH + k],
                           0.5f * Whh[(3 * NH + j) * NH + k]);
        }
        float h = h_in[b * NH + j];
        float c = c_in[b * NH + j];
        const int base_idx = b * NH + j;
        const int u = cw * NH + j;

        for (int cch = 0; cch < NCH; cch++) {
            const int buf = cch & 1;
            const int t0  = cch * CH;
            if (ld_acq_sh(&ready) < cch + 1) {
                while (ld_acq_sh(&ready) < cch + 1) __nanosleep(32);
            }
            const float4* xb = &gbuf[buf][0][u];
            // 2-deep software pipeline on gate loads
            ull p01, p23, q01, q23, n01, n23;
            lds_v2u64(p01, p23, xb);
            lds_v2u64(q01, q23, xb + (EPB * NH));
            #pragma unroll
            for (int s = 0; s < CH; s++) {
                if (s + 2 < CH) lds_v2u64(n01, n23, xb + (s + 2) * (EPB * NH));
                LSTM_STEP_P(p01, p23, t0 + s);
                p01 = q01; p23 = q23;
                q01 = n01; q23 = n23;
            }
            __syncwarp();
            if (lane == 0) red_rel_sh(&done, 1);
        }

        if (valid) {
            out[(size_t)T_LEN * STRIDE + base_idx]          = h;  // hn
            out[(size_t)T_LEN * STRIDE + STRIDE + base_idx] = c;  // cn
        }
    } else {
        // ====================== PRODUCER WARP (wid 0-3) ======================
        // Warp w owns 16 chunk-rows [w*16, w*16+16); 5 n-tiles x 3 k-tiles x
        // 3 split terms. B fragments hoisted to registers (loop-invariant).
        const int sr = tid >> 1;
        const int sp = tid & 1;
        const int k2b = sp ? 11 : 0;
        const int k2n = sp ? 10 : 11;
        const float2* xsrc0 = (const float2*)
            (x + ((size_t)(sr >> 2) * B_SZ + (b0 + (sr & 3))) * NIN) + k2b;
        const size_t chstep = (size_t)CH * B_SZ * NIN / 2;

        const int g   = lane >> 2;          // fragment group row
        const int tig = lane & 3;           // thread-in-group

        const unsigned abase  = tb + AH_O + (w * 16 + g) * 112 + tig * 4;
        const unsigned albase = abase + (AL_O - AH_O);

        // ---- hoist B fragments (hi & lo) into registers, once ----
        unsigned bh0[5][3], bh1[5][3], bl0[5][3], bl1[5][3];
        #pragma unroll
        for (int nt = 0; nt < 5; nt++) {
            const unsigned bhb = tb + BH_O + (nt * 8 + g) * 112 + tig * 4;
            const unsigned blb = bhb + (BL_O - BH_O);
            #pragma unroll
            for (int kt = 0; kt < 3; kt++) {
                bh0[nt][kt] = lds_b32(bhb + kt * 32);
                bh1[nt][kt] = lds_b32(bhb + kt * 32 + 16);
                bl0[nt][kt] = lds_b32(blb + kt * 32);
                bl1[nt][kt] = lds_b32(blb + kt * 32 + 16);
            }
        }

        // ---- prologue: stage A chunk 0 ----
        {
            float2 xr[11];
            #pragma unroll
            for (int q = 0; q < 11; q++) if (q < k2n) xr[q] = xsrc0[q];
            #pragma unroll
            for (int q = 0; q < 11; q++) {
                if (q < k2n) {
                    unsigned hp = cvt_bf16x2(xr[q].y, xr[q].x);
                    float l0 = xr[q].x - __uint_as_float(hp << 16);
                    float l1 = xr[q].y - __uint_as_float(hp & 0xFFFF0000u);
                    unsigned lp = cvt_bf16x2(l1, l0);
                    *(unsigned*)(tiles + AH_O + sr * 112 + (k2b + q) * 4) = hp;
                    *(unsigned*)(tiles + AL_O + sr * 112 + (k2b + q) * 4) = lp;
                }
            }
            if (sp == 0) {
                *(unsigned*)(tiles + AH_O + sr * 112 + 84) = 0x00003F80u; // bias col = 1.0
                *(unsigned*)(tiles + AL_O + sr * 112 + 84) = 0u;
            }
            asm volatile("bar.sync 1, 128;" ::: "memory");
        }

        for (int cch = 0; cch < NCH; cch++) {
            const int buf = cch & 1;

            // prefetch next chunk's x (LDG overlaps mma mainloop)
            float2 xr[11];
            if (cch + 1 < NCH) {
                const float2* src = xsrc0 + (size_t)(cch + 1) * chstep;
                #pragma unroll
                for (int q = 0; q < 11; q++) if (q < k2n) xr[q] = src[q];
            }

            // gbuf slot free? (lag-2 ring)
            if (cch >= 2) {
                const int need = EPB * (cch - 1);
                if (ld_vol_sh(&done) < need) {
                    while (ld_vol_sh(&done) < need) __nanosleep(64);
                }
            }

            // ---- load A fragments (hi & lo) for this warp's 16 rows ----
            unsigned ah[3][4], al[3][4];
            #pragma unroll
            for (int kt = 0; kt < 3; kt++) {
                ah[kt][0] = lds_b32(abase  + kt * 32);
                ah[kt][1] = lds_b32(abase  + kt * 32 + 896);
                ah[kt][2] = lds_b32(abase  + kt * 32 + 16);
                ah[kt][3] = lds_b32(abase  + kt * 32 + 912);
                al[kt][0] = lds_b32(albase + kt * 32);
                al[kt][1] = lds_b32(albase + kt * 32 + 896);
                al[kt][2] = lds_b32(albase + kt * 32 + 16);
                al[kt][3] = lds_b32(albase + kt * 32 + 912);
            }

            // ---- mma over 5 n-tiles, 3 k-tiles, 3 split terms ----
            #pragma unroll
            for (int nt = 0; nt < 5; nt++) {
                float d0 = 0.f, d1 = 0.f, d2 = 0.f, d3 = 0.f;
                #pragma unroll
                for (int kt = 0; kt < 3; kt++) {
                    mma_bf16(d0, d1, d2, d3,
                             ah[kt][0], ah[kt][1], ah[kt][2], ah[kt][3],
                             bh0[nt][kt], bh1[nt][kt]);
                    mma_bf16(d0, d1, d2, d3,
                             ah[kt][0], ah[kt][1], ah[kt][2], ah[kt][3],
                             bl0[nt][kt], bl1[nt][kt]);
                    mma_bf16(d0, d1, d2, d3,
                             al[kt][0], al[kt][1], al[kt][2], al[kt][3],
                             bh0[nt][kt], bh1[nt][kt]);
                }
                // ---- scatter D pairs into the gate ring ----
                const int n0 = nt * 8 + 2 * tig;
                if (n0 < 36) {
                    const int j  = n0 >> 2;
                    const int hs = (n0 & 3) >> 1;
                    const int r0 = w * 16 + g;
                    const int r1 = r0 + 8;
                    float2* p0 = (float2*)&gbuf[buf][r0 >> 2][(r0 & 3) * NH + j] + hs;
                    float2* p1 = (float2*)&gbuf[buf][r1 >> 2][(r1 & 3) * NH + j] + hs;
                    *p0 = make_float2(d0, d1);
                    *p1 = make_float2(d2, d3);
                }
            }

            asm volatile("bar.sync 1, 128;" ::: "memory");
            if (tid == 0) st_rel_sh(&ready, cch + 1);

            // ---- stage next chunk's A from registers ----
            if (cch + 1 < NCH) {
                #pragma unroll
                for (int q = 0; q < 11; q++) {
                    if (q < k2n) {
                        unsigned hp = cvt_bf16x2(xr[q].y, xr[q].x);
                        float l0 = xr[q].x - __uint_as_float(hp << 16);
                        float l1 = xr[q].y - __uint_as_float(hp & 0xFFFF0000u);
                        unsigned lp = cvt_bf16x2(l1, l0);
                        *(unsigned*)(tiles + AH_O + sr * 112 + (k2b + q) * 4) = hp;
                        *(unsigned*)(tiles + AL_O + sr * 112 + (k2b + q) * 4) = lp;
                    }
                }
                if (sp == 0) {
                    *(unsigned*)(tiles + AH_O + sr * 112 + 84) = 0x00003F80u;
                    *(unsigned*)(tiles + AL_O + sr * 112 + 84) = 0u;
                }
                asm volatile("bar.sync 1, 128;" ::: "memory");
            }
        }
    }
}

// ---------------------------------------------------------------------------
extern "C" void kernel_launch(void* const* d_in, const int* in_sizes, int n_in,
                              void* d_out, int out_size) {
    const float* x   = (const float*)d_in[0];
    const float* h   = (const float*)d_in[1];
    const float* c   = (const float*)d_in[2];
    const float* Wih = (const float*)d_in[3];
    const float* Whh = (const float*)d_in[4];
    const float* bih = (const float*)d_in[5];
    const float* bhh = (const float*)d_in[6];
    float* out = (float*)d_out;

    lstm_fused_kernel<<<NBLK, 256>>>(x, h, c, Wih, Whh, bih, bhh, out);
}